// round 16
// baseline (speedup 1.0000x reference)
#include <cuda_runtime.h>
#include <cstdint>
#include <cstddef>

#define BS      64
#define NVAL    25200
#define KCAND   512
#define MAXDET  300
#define CONF_T  0.25f
#define IOU_T   0.45f
#define MAX_WH  7680.0f
#define NBIN    4096
#define CAP     6144
#define ECAP    8192

typedef unsigned long long u64;

// ---- static device scratch (no allocation anywhere; zero-initialized) ----
__device__ u64          g_keys[(size_t)BS * NVAL];        // 12.9 MB
__device__ unsigned int g_hist[BS][NBIN];                 // self-resetting

// ---------------------------------------------------------------------------
// K1: scores -> 64-bit sortable keys + per-image 4096-bin MSB histogram.
// ---------------------------------------------------------------------------
__global__ void score_kernel(const float* __restrict__ pred) {
    const int b = blockIdx.y;
    const int i = blockIdx.x * 1024 + threadIdx.x;
    __shared__ unsigned int sh[NBIN];
    for (int t = threadIdx.x; t < NBIN; t += 1024) sh[t] = 0u;
    __syncthreads();

    bool act = (i < NVAL);
    unsigned int am = __ballot_sync(0xffffffffu, act);
    if (act) {
        const float4* p = (const float4*)(pred + ((size_t)b * NVAL + i) * 8);
        float4 c = p[1];                           // obj, cls0, cls1, cls2
        float s0 = __fmul_rn(c.x, c.y);
        float s1 = __fmul_rn(c.x, c.z);
        float s2 = __fmul_rn(c.x, c.w);
        float best = s0;
        if (s1 > best) best = s1;
        if (s2 > best) best = s2;
        unsigned int bits = __float_as_uint(best); // scores >= 0 -> monotonic
        g_keys[(size_t)b * NVAL + i] =
            ((u64)bits << 32) | (0xFFFFFFFFu - (unsigned int)i);
        unsigned int bin = bits >> 20;             // 12-bit MSB digit
        unsigned int mm = __match_any_sync(am, bin);
        if ((threadIdx.x & 31) == (__ffs(mm) - 1))
            atomicAdd(&sh[bin], (unsigned int)__popc(mm));
    }
    __syncthreads();
    for (int t = threadIdx.x; t < NBIN; t += 1024)
        if (sh[t]) atomicAdd(&g_hist[b][t], sh[t]);
}

// ---------------------------------------------------------------------------
// K2 (per-image, fused): shuffle rank-sort top-512 + class-partitioned
//     EDGE-LIST NMS (mask fallback) + pack. 1 block/image, 1024 threads.
// Dynamic smem 106496 B (same layout; tm region doubles as edge buffer,
// buf region doubles as sorted-edge buffer after select).
// ---------------------------------------------------------------------------
extern __shared__ unsigned char smdyn[];

__global__ void __launch_bounds__(1024, 1)
perimage_kernel(const float* __restrict__ pred, float* __restrict__ out) {
    const int b   = blockIdx.x;
    const int tid = threadIdx.x;
    const int lane = tid & 31, wrp = tid >> 5;

    u64*    buf    = (u64*)(smdyn);                       // [CAP]
    u64*    tm     = (u64*)(smdyn + 49152);               // fallback mask
    unsigned int* edges  = (unsigned int*)(smdyn + 49152); // [ECAP] (alias tm)
    unsigned int* esort  = (unsigned int*)(smdyn);         // alias buf (free after select)
    u64*    keysS  = (u64*)(smdyn + 81920);
    float4* sbox   = (float4*)(smdyn + 86016);
    float*  sar    = (float*)(smdyn + 94208);
    float*  scoreS = (float*)(smdyn + 96256);
    int*    cidS   = (int*)(smdyn + 98304);
    int*    topiS  = (int*)(smdyn + 100352);
    int*    memberL= (int*)(smdyn + 102400);
    int*    myrank = (int*)(smdyn + 104448);

    __shared__ unsigned int warpTot[32];
    __shared__ int warpPfx[32];
    __shared__ int s_classBase[4];
    __shared__ unsigned int hist[257];
    __shared__ u64 s_pf;
    __shared__ int s_b12, s_need, s_shift, s_done, s_nv, s_nconf;
    __shared__ unsigned int s_cnt, s_ecnt;
    __shared__ unsigned int nz32[16], valid32[16];

    const u64* keys = g_keys + (size_t)b * NVAL;

    // ========== 1. threshold digit from pre-hist ==========
    unsigned int h0, h1, h2, h3;
    {
        int base = tid * 4;
        h0 = g_hist[b][base];     g_hist[b][base]     = 0u;
        h1 = g_hist[b][base + 1]; g_hist[b][base + 1] = 0u;
        h2 = g_hist[b][base + 2]; g_hist[b][base + 2] = 0u;
        h3 = g_hist[b][base + 3]; g_hist[b][base + 3] = 0u;
    }
    unsigned int s = h0 + h1 + h2 + h3;
    unsigned int v = s;
    #pragma unroll
    for (int off = 1; off < 32; off <<= 1) {
        unsigned int o = __shfl_down_sync(0xffffffffu, v, off);
        if (lane + off < 32) v += o;
    }
    if (lane == 0) warpTot[wrp] = v;
    if (tid == 0) { s_cnt = 0u; s_ecnt = 0u; }
    __syncthreads();
    if (tid < 32) {
        unsigned int wv = warpTot[tid];
        unsigned int x = wv;
        #pragma unroll
        for (int off = 1; off < 32; off <<= 1) {
            unsigned int o = __shfl_down_sync(0xffffffffu, x, off);
            if (tid + off < 32) x += o;
        }
        warpTot[tid] = x - wv;                // sum over warps > tid
    }
    __syncthreads();
    {
        unsigned int after = v + warpTot[wrp] - s;   // sum over threads > tid
        unsigned int sfx4 = after;
        unsigned int sfx3 = sfx4 + h3;
        unsigned int sfx2 = sfx3 + h2;
        unsigned int sfx1 = sfx2 + h1;
        unsigned int sfx0 = sfx1 + h0;
        unsigned int sfx[5] = {sfx0, sfx1, sfx2, sfx3, sfx4};
        unsigned int hh[4] = {h0, h1, h2, h3};
        #pragma unroll
        for (int k = 0; k < 4; ++k) {
            if ((int)sfx[k] >= KCAND && (int)sfx[k + 1] < KCAND) {  // unique
                s_b12  = tid * 4 + k;
                s_need = KCAND - (int)sfx[k + 1];
                s_done = ((int)hh[k] == KCAND - (int)sfx[k + 1]);
                (void)s_done;
            }
        }
    }
    __syncthreads();

    // ========== 2. one global pass (vectorized): digit >= b12 -> buf ==========
    const unsigned int b12 = (unsigned int)s_b12;
    {
        const ulonglong2* keys2 = (const ulonglong2*)keys;
        for (int ii = tid; ii < NVAL / 2; ii += 1024) {
            ulonglong2 kv = keys2[ii];
            if ((unsigned int)(kv.x >> 52) >= b12) {
                unsigned int p = atomicAdd(&s_cnt, 1u);
                if (p < CAP) buf[p] = kv.x;
            }
            if ((unsigned int)(kv.y >> 52) >= b12) {
                unsigned int p = atomicAdd(&s_cnt, 1u);
                if (p < CAP) buf[p] = kv.y;
            }
        }
    }
    __syncthreads();
    const int n = (int)s_cnt;

    if (n <= CAP) {
        // ===== 3a. warp-tiled shuffle rank-sort =====
        int nPad = (n + 31) & ~31;
        for (int t = n + tid; t < nPad; t += 1024) buf[t] = 0ull;  // pad keys
        __syncthreads();
        for (int base = wrp * 32; base < nPad; base += 1024) {
            int t = base + lane;          // full warp active, t < nPad
            u64 me = buf[t];
            int rank = 0;
            for (int jt = 0; jt < nPad; jt += 32) {
                u64 kv = buf[jt + lane];
                #pragma unroll
                for (int l = 0; l < 32; ++l) {
                    u64 o = __shfl_sync(0xffffffffu, kv, l);
                    rank += (o > me);
                }
            }
            if (t < n && rank < KCAND) keysS[rank] = me;
        }
    } else {
        // ===== 3b. fallback: global radix refinement (rare, exact) =====
        if (tid == 0) { s_pf = (u64)b12; s_shift = 52; s_done = 0; }
        __syncthreads();
        for (int lvl = 0; lvl < 8 && !s_done; ++lvl) {
            u64 pf    = s_pf;
            int shift = s_shift;
            int w     = (shift >= 8) ? 8 : shift;
            int nsh   = shift - w;
            if (tid < 257) hist[tid] = 0u;
            __syncthreads();
            for (int ii = tid; ii < NVAL; ii += 1024) {
                u64 kk = keys[ii];
                if ((kk >> shift) == pf)
                    atomicAdd(&hist[(unsigned int)(kk >> nsh) & ((1u << w) - 1u)], 1u);
            }
            __syncthreads();
            #pragma unroll
            for (int off = 1; off < 256; off <<= 1) {
                unsigned int vv = 0;
                if (tid < 256)
                    vv = hist[tid] + ((tid + off < 256) ? hist[tid + off] : 0u);
                __syncthreads();
                if (tid < 256) hist[tid] = vv;
                __syncthreads();
            }
            const int need = s_need;
            __syncthreads();
            if (tid < 256) {
                unsigned int sfx = hist[tid], sfx1 = hist[tid + 1];
                if ((int)sfx >= need && (int)sfx1 < need) {
                    int hbin     = (int)(sfx - sfx1);
                    int need_new = need - (int)sfx1;
                    s_pf    = (pf << w) | (unsigned int)tid;
                    s_shift = nsh;
                    s_need  = need_new;
                    if (hbin == need_new || nsh == 0) s_done = 1;
                }
            }
            __syncthreads();
        }
        if (tid == 0) s_cnt = 0u;
        __syncthreads();
        {
            u64 pf    = s_pf;
            int shift = s_shift;
            for (int ii = tid; ii < NVAL; ii += 1024) {
                u64 kk = keys[ii];
                unsigned int d = (unsigned int)(kk >> 52);
                if (d > b12 || (d == b12 && (kk >> shift) >= pf))
                    buf[atomicAdd(&s_cnt, 1u)] = kk;   // exactly 512
            }
        }
        __syncthreads();
        if (tid < KCAND) {
            u64 me = buf[tid];
            int rank = 0;
            #pragma unroll 4
            for (int j = 0; j < KCAND; ++j) rank += (buf[j] > me);
            keysS[rank] = me;
        }
    }
    __syncthreads();

    // ========== 4. extract candidates into smem + nconf prefix ==========
    if (tid < KCAND) {
        u64 kk = keysS[tid];
        int   idx = (int)(0xFFFFFFFFu - (unsigned int)kk);
        float sc  = __uint_as_float((unsigned int)(kk >> 32));
        const float4* p = (const float4*)(pred + ((size_t)b * NVAL + idx) * 8);
        float4 a = p[0];                 // cx, cy, w, h
        float4 c = p[1];                 // obj, cls0..2
        float s0 = __fmul_rn(c.x, c.y);
        float s1 = __fmul_rn(c.x, c.z);
        float s2 = __fmul_rn(c.x, c.w);
        int cid = 0; float bv = s0;
        if (s1 > bv) { bv = s1; cid = 1; }
        if (s2 > bv) { bv = s2; cid = 2; }
        float hw  = __fmul_rn(a.z, 0.5f), hh = __fmul_rn(a.w, 0.5f);
        float bx1 = __fsub_rn(a.x, hw),  by1 = __fsub_rn(a.y, hh);
        float bx2 = __fadd_rn(a.x, hw),  by2 = __fadd_rn(a.y, hh);
        float off = __fmul_rn((float)cid, MAX_WH);
        float X1 = __fadd_rn(bx1, off), Y1 = __fadd_rn(by1, off);
        float X2 = __fadd_rn(bx2, off), Y2 = __fadd_rn(by2, off);
        sbox[tid]   = make_float4(X1, Y1, X2, Y2);
        sar[tid]    = __fmul_rn(__fsub_rn(X2, X1), __fsub_rn(Y2, Y1));
        scoreS[tid] = sc;
        cidS[tid]   = cid;
        topiS[tid]  = idx;

        bool c0 = sc > CONF_T;
        bool c1 = (tid < KCAND - 1)
                ? (__uint_as_float((unsigned int)(keysS[tid + 1] >> 32)) > CONF_T)
                : false;
        if (c0 && !c1) s_nconf = tid + 1;          // unique crossing
        if (tid == 0 && !c0) s_nconf = 0;
    }
    __syncthreads();

    // ========== 4b. per-class member lists (order-preserving) ==========
    if (tid == 0) s_classBase[0] = 0;
    {
        int myc = (tid < KCAND) ? cidS[tid] : -1;
        for (int c = 0; c < 3; ++c) {
            bool pred2 = (myc == c);
            unsigned int m = __ballot_sync(0xffffffffu, pred2);
            int lanePfx = __popc(m & ((1u << lane) - 1u));
            if (lane == 0) warpTot[wrp] = __popc(m);
            __syncthreads();
            if (tid == 0) {
                int run = 0;
                for (int w2 = 0; w2 < 32; ++w2) { warpPfx[w2] = run; run += (int)warpTot[w2]; }
                s_classBase[c + 1] = s_classBase[c] + run;
            }
            __syncthreads();
            if (pred2) {
                int pos = s_classBase[c] + warpPfx[wrp] + lanePfx;
                memberL[pos] = tid;
                myrank[tid]  = pos;
            }
            __syncthreads();
        }
    }

    // ========== 5. class-partitioned suppression EDGE collection ==========
    {
        const int half = tid >> 9;
        const int i    = tid & (KCAND - 1);
        const int c    = cidS[i];
        const int mp   = myrank[i];
        const int end  = s_classBase[c + 1];
        float4 bi = sbox[i];
        float  aa = sar[i];
        for (int mj = mp + 1 + half; mj < end; mj += 2) {
            int j = memberL[mj];                      // j > i (ascending in class)
            float4 bj = sbox[j];
            float ltx = fmaxf(bi.x, bj.x), lty = fmaxf(bi.y, bj.y);
            float rbx = fminf(bi.z, bj.z), rby = fminf(bi.w, bj.w);
            float iw = fmaxf(__fsub_rn(rbx, ltx), 0.0f);
            float ih = fmaxf(__fsub_rn(rby, lty), 0.0f);
            float inter = __fmul_rn(iw, ih);
            if (inter > 0.0f) {                       // inter==0 -> iou==0 exactly
                float denom = __fadd_rn(__fsub_rn(__fadd_rn(aa, sar[j]), inter), 1e-7f);
                if (__fdiv_rn(inter, denom) > IOU_T) {
                    unsigned int p = atomicAdd(&s_ecnt, 1u);
                    if (p < ECAP) edges[p] = ((unsigned int)i << 9) | (unsigned int)j;
                }
            }
        }
    }
    __syncthreads();
    const int ne = (int)s_ecnt;

    if (ne <= ECAP) {
        // ===== 6a. sort edges ascending (distinct values) =====
        for (int t = tid; t < ne; t += 1024) {
            unsigned int me = edges[t];
            int rank = 0;
            #pragma unroll 4
            for (int j = 0; j < ne; ++j) rank += (edges[j] < me);
            esort[rank] = me;
        }
        __syncthreads();

        // ===== 7a. serial edge walk (sup in registers, unrolled select) =====
        if (tid == 0) {
            u64 sup[8] = {0,0,0,0,0,0,0,0};
            for (int t = 0; t < ne; ++t) {
                unsigned int e = esort[t];
                int i = (int)(e >> 9), j = (int)(e & 511u);
                int wi = i >> 6, wj = j >> 6;
                u64 bi = 1ull << (i & 63), bj = 1ull << (j & 63);
                u64 supw = 0;
                #pragma unroll
                for (int q = 0; q < 8; ++q) if (q == wi) supw = sup[q];
                if ((supw & bi) == 0ull) {
                    #pragma unroll
                    for (int q = 0; q < 8; ++q) if (q == wj) sup[q] |= bj;
                }
            }
            int nconf = s_nconf;
            int nv = 0;
            #pragma unroll
            for (int w = 0; w < 8; ++w) {
                int lo = nconf - (w << 6);
                u64 conf = (lo >= 64) ? ~0ull : ((lo <= 0) ? 0ull : ((1ull << lo) - 1ull));
                u64 valid = (~sup[w]) & conf;
                if (w == 0) valid |= 1ull;     // index 0: never suppressed, rank 1
                valid32[2*w]     = (unsigned int)valid;
                valid32[2*w + 1] = (unsigned int)(valid >> 32);
                nv += __popcll(valid);
            }
            s_nv = nv;
        }
    } else {
        // ===== 6b/7b. fallback: word-major mask + sparse greedy (exact) =====
        for (int t = tid; t < KCAND * 8; t += 1024) tm[t] = 0ull;
        __syncthreads();
        {
            const int half = tid >> 9;
            const int i    = tid & (KCAND - 1);
            const int c    = cidS[i];
            const int mp   = myrank[i];
            const int end  = s_classBase[c + 1];
            float4 bi = sbox[i];
            float  aa = sar[i];
            for (int mj = mp + 1 + half; mj < end; mj += 2) {
                int j = memberL[mj];
                float4 bj = sbox[j];
                float ltx = fmaxf(bi.x, bj.x), lty = fmaxf(bi.y, bj.y);
                float rbx = fminf(bi.z, bj.z), rby = fminf(bi.w, bj.w);
                float iw = fmaxf(__fsub_rn(rbx, ltx), 0.0f);
                float ih = fmaxf(__fsub_rn(rby, lty), 0.0f);
                float inter = __fmul_rn(iw, ih);
                if (inter > 0.0f) {
                    float denom = __fadd_rn(__fsub_rn(__fadd_rn(aa, sar[j]), inter), 1e-7f);
                    if (__fdiv_rn(inter, denom) > IOU_T)
                        atomicOr(&tm[(j >> 6) * KCAND + i], 1ull << (j & 63));
                }
            }
        }
        __syncthreads();
        if (tid < KCAND) {
            u64 o = tm[tid]            | tm[KCAND     + tid] |
                    tm[2*KCAND + tid]  | tm[3*KCAND   + tid] |
                    tm[4*KCAND + tid]  | tm[5*KCAND   + tid] |
                    tm[6*KCAND + tid]  | tm[7*KCAND   + tid];
            unsigned bnz = __ballot_sync(0xffffffffu, o != 0ull);
            if ((tid & 31) == 0) nz32[tid >> 5] = bnz;
        }
        __syncthreads();
        if (tid == 0) {
            u64 sup[8] = {0,0,0,0,0,0,0,0};
            u64 nz[8];
            #pragma unroll
            for (int q = 0; q < 8; ++q)
                nz[q] = (u64)nz32[2*q] | ((u64)nz32[2*q + 1] << 32);
            #pragma unroll
            for (int w = 0; w < 8; ++w) {
                u64 x = nz[w] & ~sup[w];
                while (x) {
                    int bb = __ffsll((long long)x) - 1;
                    int i = (w << 6) + bb;
                    #pragma unroll
                    for (int q = 0; q < 8; ++q) sup[q] |= tm[q * KCAND + i];
                    u64 above = (bb == 63) ? 0ull : (~0ull << (bb + 1));
                    x = nz[w] & ~sup[w] & above;
                }
            }
            int nconf = s_nconf;
            int nv = 0;
            #pragma unroll
            for (int w = 0; w < 8; ++w) {
                int lo = nconf - (w << 6);
                u64 conf = (lo >= 64) ? ~0ull : ((lo <= 0) ? 0ull : ((1ull << lo) - 1ull));
                u64 valid = (~sup[w]) & conf;
                if (w == 0) valid |= 1ull;
                valid32[2*w]     = (unsigned int)valid;
                valid32[2*w + 1] = (unsigned int)(valid >> 32);
                nv += __popcll(valid);
            }
            s_nv = nv;
        }
    }
    __syncthreads();

    // ========== 8. parallel pack (valid asc, then invalid asc) ==========
    if (tid < MAXDET) {
        int nv = s_nv;
        bool isv = tid < nv;
        int r = isv ? tid : tid - nv;
        int k = -1;
        #pragma unroll
        for (int wi = 0; wi < 16; ++wi) {
            unsigned wv = valid32[wi];
            if (!isv) wv = ~wv;
            int c = __popc(wv);
            if (k < 0) {
                if (r < c) k = wi * 32 + __fns(wv, 0, r + 1);
                else       r -= c;
            }
        }
        int gi = topiS[k];
        float b0 = 0.f, b1 = 0.f, b2 = 0.f, b3 = 0.f, sc = 0.f;
        if (isv) {
            const float4* p = (const float4*)(pred + ((size_t)b * NVAL + gi) * 8);
            float4 a = p[0];
            float hw = __fmul_rn(a.z, 0.5f), hh = __fmul_rn(a.w, 0.5f);
            b0 = __fsub_rn(a.x, hw); b1 = __fsub_rn(a.y, hh);
            b2 = __fadd_rn(a.x, hw); b3 = __fadd_rn(a.y, hh);
            sc = scoreS[k];
        }
        const size_t scoresOff = (size_t)BS * MAXDET * 4;
        const size_t clsOff    = scoresOff + (size_t)BS * MAXDET;
        const size_t idsOff    = clsOff    + (size_t)BS * MAXDET;
        const size_t valOff    = idsOff    + (size_t)BS * MAXDET;
        size_t rr = (size_t)b * MAXDET + tid;
        out[rr * 4 + 0] = b0;
        out[rr * 4 + 1] = b1;
        out[rr * 4 + 2] = b2;
        out[rr * 4 + 3] = b3;
        out[scoresOff + rr] = sc;
        out[clsOff + rr] = (float)cidS[k];     // NOT zeroed for pads (ref semantics)
        out[idsOff + rr] = (float)(gi / 3);    // NOT zeroed for pads (ref semantics)
        out[valOff + rr] = isv ? 1.0f : 0.0f;
    }
}

// ---------------------------------------------------------------------------
extern "C" void kernel_launch(void* const* d_in, const int* in_sizes, int n_in,
                              void* d_out, int out_size) {
    (void)in_sizes; (void)n_in; (void)out_size;
    const float* pred = (const float*)d_in[0];
    float* out = (float*)d_out;

    score_kernel<<<dim3(25, BS), 1024>>>(pred);
    cudaFuncSetAttribute(perimage_kernel,
                         cudaFuncAttributeMaxDynamicSharedMemorySize, 106496);
    perimage_kernel<<<BS, 1024, 106496>>>(pred, out);
}